// round 11
// baseline (speedup 1.0000x reference)
#include <cuda_runtime.h>
#include <cuda_bf16.h>

// EmbeddingSumConcat: out[b, f*E+e] = sum_{l < lengths[b,f]} tables[f, ids[b,f,l], e]
// B=4096, F=32, V=100000, L=20, E=64. ids/lengths int32 (JAX x64 disabled),
// tables/out fp32.
//
// R11: R10 (LDG.256 gathers, 54.0us) with the occupancy cap fixed:
// __launch_bounds__(128,8) silently limited the SM to 32 warps. Now
// block=256, min 8 blocks -> 64-warp ceiling, same 64-reg budget per thread.

#define EB_B 4096
#define EB_F 32
#define EB_V 100000
#define EB_L 20
#define EB_E 64
#define EB_V8 (EB_E / 8)     // 8 lanes of 8 floats (32B) per row

__global__ __launch_bounds__(256, 8) void embbag_kernel(
    const int*   __restrict__ ids,      // int32 [B, F, L]
    const int*   __restrict__ lengths,  // int32 [B, F]
    const float* __restrict__ tables,   // fp32  [F, V, E]
    float*       __restrict__ out)      // fp32  [B, F, E]
{
    int tid = blockIdx.x * 256 + threadIdx.x;       // 0 .. B*F*8-1
    int v    = tid & (EB_V8 - 1);                   // 32B lane in row (0..7)
    int cell = tid >> 3;                            // f-major: cell = f*B + b
    int b    = cell & (EB_B - 1);                   // B = 4096 = 2^12
    int f    = cell >> 12;

    size_t bf = (size_t)b * EB_F + f;
    int n = lengths[bf];                            // 0..20
    const float* base = tables + (size_t)f * EB_V * EB_E + v * 8;

    // Ids for this cell: 80 bytes, 16B-aligned (bf*80). 5x int4 loads,
    // hardware-broadcast across the 8 lanes of the cell.
    const int4* idp4 = (const int4*)(ids + bf * EB_L);
    int idbuf[EB_L];
#pragma unroll
    for (int q = 0; q < EB_L / 4; q++) {
        int4 w = __ldg(&idp4[q]);
        idbuf[q * 4 + 0] = w.x;
        idbuf[q * 4 + 1] = w.y;
        idbuf[q * 4 + 2] = w.z;
        idbuf[q * 4 + 3] = w.w;
    }

    float a0 = 0.f, a1 = 0.f, a2 = 0.f, a3 = 0.f;
    float a4 = 0.f, a5 = 0.f, a6 = 0.f, a7 = 0.f;
#pragma unroll
    for (int l = 0; l < EB_L; l++) {
        if (l < n) {
            const float* p = base + (size_t)idbuf[l] * EB_E;
            unsigned u0, u1, u2, u3, u4, u5, u6, u7;
            asm volatile(
                "ld.global.nc.L2::evict_last.v8.b32 "
                "{%0,%1,%2,%3,%4,%5,%6,%7}, [%8];"
                : "=r"(u0), "=r"(u1), "=r"(u2), "=r"(u3),
                  "=r"(u4), "=r"(u5), "=r"(u6), "=r"(u7)
                : "l"(p));
            a0 += __uint_as_float(u0); a1 += __uint_as_float(u1);
            a2 += __uint_as_float(u2); a3 += __uint_as_float(u3);
            a4 += __uint_as_float(u4); a5 += __uint_as_float(u5);
            a6 += __uint_as_float(u6); a7 += __uint_as_float(u7);
        }
    }

    // Streaming stores: written once, never re-read.
    float4* op = (float4*)(out + bf * EB_E + v * 8);
    __stcs(&op[0], make_float4(a0, a1, a2, a3));
    __stcs(&op[1], make_float4(a4, a5, a6, a7));
}

extern "C" void kernel_launch(void* const* d_in, const int* in_sizes, int n_in,
                              void* d_out, int out_size) {
    const int*   ids     = (const int*)d_in[0];     // int32 [B,F,L]
    const int*   lengths = (const int*)d_in[1];     // int32 [B,F]
    const float* tables  = (const float*)d_in[2];   // fp32  [F,V,E]
    float*       out     = (float*)d_out;           // fp32  [B,F*E]

    int total = EB_B * EB_F * EB_V8;                // 1,048,576 threads
    embbag_kernel<<<total / 256, 256>>>(ids, lengths, tables, out);
}

// round 12
// speedup vs baseline: 1.2884x; 1.2884x over previous
#include <cuda_runtime.h>
#include <cuda_bf16.h>

// EmbeddingSumConcat: out[b, f*E+e] = sum_{l < lengths[b,f]} tables[f, ids[b,f,l], e]
// B=4096, F=32, V=100000, L=20, E=64. ids/lengths int32 (JAX x64 disabled),
// tables/out fp32.
//
// R12: R10's LDG.256 gathers, but the 20-reg idbuf (duplicated across all 8
// lanes of a cell) moves to shared memory (16 cells x 80B = 1280B/block).
// Freed registers go to +50% occupancy (48 warps/SM at 42-reg cap) while
// keeping ~3 LDG.256 batched in flight per thread.

#define EB_B 4096
#define EB_F 32
#define EB_V 100000
#define EB_L 20
#define EB_E 64
#define EB_V8 (EB_E / 8)     // 8 lanes of 8 floats (32B) per row
#define EB_CPB 16            // cells per 128-thread block

__global__ __launch_bounds__(128, 12) void embbag_kernel(
    const int*   __restrict__ ids,      // int32 [B, F, L]
    const int*   __restrict__ lengths,  // int32 [B, F]
    const float* __restrict__ tables,   // fp32  [F, V, E]
    float*       __restrict__ out)      // fp32  [B, F, E]
{
    __shared__ __align__(16) int s_ids[EB_CPB][EB_L];   // 1280 B

    int t    = threadIdx.x;
    int tid  = blockIdx.x * 128 + t;                // 0 .. B*F*8-1
    int v    = tid & (EB_V8 - 1);                   // 32B lane in row (0..7)
    int cl   = t >> 3;                              // cell within block (0..15)
    int cell = tid >> 3;                            // f-major: cell = f*B + b
    int b    = cell & (EB_B - 1);                   // B = 4096 = 2^12
    int f    = cell >> 12;

    size_t bf = (size_t)b * EB_F + f;
    int n = lengths[bf];                            // 0..20
    const float* base = tables + (size_t)f * EB_V * EB_E + v * 8;

    // Cooperative id load: 80B per cell = 5 int4; lanes 0-4 of each cell each
    // fetch one int4 into smem. Loader lanes and readers share a warp
    // (4 cells per warp), so __syncwarp suffices.
    if (v < 5) {
        const int4* idp4 = (const int4*)(ids + bf * EB_L);
        ((int4*)s_ids[cl])[v] = __ldg(&idp4[v]);
    }
    __syncwarp();

    float a0 = 0.f, a1 = 0.f, a2 = 0.f, a3 = 0.f;
    float a4 = 0.f, a5 = 0.f, a6 = 0.f, a7 = 0.f;
#pragma unroll
    for (int l = 0; l < EB_L; l++) {
        if (l < n) {
            int id = s_ids[cl][l];                  // LDS broadcast, conflict-free
            const float* p = base + (size_t)id * EB_E;
            unsigned u0, u1, u2, u3, u4, u5, u6, u7;
            asm volatile(
                "ld.global.nc.L2::evict_last.v8.b32 "
                "{%0,%1,%2,%3,%4,%5,%6,%7}, [%8];"
                : "=r"(u0), "=r"(u1), "=r"(u2), "=r"(u3),
                  "=r"(u4), "=r"(u5), "=r"(u6), "=r"(u7)
                : "l"(p));
            a0 += __uint_as_float(u0); a1 += __uint_as_float(u1);
            a2 += __uint_as_float(u2); a3 += __uint_as_float(u3);
            a4 += __uint_as_float(u4); a5 += __uint_as_float(u5);
            a6 += __uint_as_float(u6); a7 += __uint_as_float(u7);
        }
    }

    // Streaming stores: written once, never re-read.
    float4* op = (float4*)(out + bf * EB_E + v * 8);
    __stcs(&op[0], make_float4(a0, a1, a2, a3));
    __stcs(&op[1], make_float4(a4, a5, a6, a7));
}

extern "C" void kernel_launch(void* const* d_in, const int* in_sizes, int n_in,
                              void* d_out, int out_size) {
    const int*   ids     = (const int*)d_in[0];     // int32 [B,F,L]
    const int*   lengths = (const int*)d_in[1];     // int32 [B,F]
    const float* tables  = (const float*)d_in[2];   // fp32  [F,V,E]
    float*       out     = (float*)d_out;           // fp32  [B,F*E]

    int total = EB_B * EB_F * EB_V8;                // 1,048,576 threads
    embbag_kernel<<<total / 128, 128>>>(ids, lengths, tables, out);
}

// round 13
// speedup vs baseline: 1.3437x; 1.0429x over previous
#include <cuda_runtime.h>
#include <cuda_bf16.h>

// EmbeddingSumConcat: out[b, f*E+e] = sum_{l < lengths[b,f]} tables[f, ids[b,f,l], e]
// B=4096, F=32, V=100000, L=20, E=64. ids/lengths int32 (JAX x64 disabled),
// tables/out fp32.
//
// R13: LDG.256 gathers + smem ids + R10's occupancy config.
// Lesson from R10/R11/R12: per-thread load-batch depth beats warp count.
// smem ids free ~20 regs/thread; __launch_bounds__(128,8) keeps the 64-reg
// cap so ptxas spends the freed budget on MORE in-flight LDG.256 batches
// (≈5-6 vs R10's ≈3) at the same 32 warps/SM.

#define EB_B 4096
#define EB_F 32
#define EB_V 100000
#define EB_L 20
#define EB_E 64
#define EB_V8 (EB_E / 8)     // 8 lanes of 8 floats (32B) per row
#define EB_CPB 16            // cells per 128-thread block

__global__ __launch_bounds__(128, 8) void embbag_kernel(
    const int*   __restrict__ ids,      // int32 [B, F, L]
    const int*   __restrict__ lengths,  // int32 [B, F]
    const float* __restrict__ tables,   // fp32  [F, V, E]
    float*       __restrict__ out)      // fp32  [B, F, E]
{
    __shared__ __align__(16) int s_ids[EB_CPB][EB_L];   // 1280 B

    int t    = threadIdx.x;
    int tid  = blockIdx.x * 128 + t;                // 0 .. B*F*8-1
    int v    = tid & (EB_V8 - 1);                   // 32B lane in row (0..7)
    int cl   = t >> 3;                              // cell within block (0..15)
    int cell = tid >> 3;                            // f-major: cell = f*B + b
    int b    = cell & (EB_B - 1);                   // B = 4096 = 2^12
    int f    = cell >> 12;

    size_t bf = (size_t)b * EB_F + f;
    int n = lengths[bf];                            // 0..20
    const float* base = tables + (size_t)f * EB_V * EB_E + v * 8;

    // Cooperative id load: 80B per cell = 5 int4; lanes 0-4 of each cell each
    // fetch one int4 into smem. Loaders and readers share a warp
    // (4 cells per warp), so __syncwarp suffices.
    if (v < 5) {
        const int4* idp4 = (const int4*)(ids + bf * EB_L);
        ((int4*)s_ids[cl])[v] = __ldg(&idp4[v]);
    }
    __syncwarp();

    float a0 = 0.f, a1 = 0.f, a2 = 0.f, a3 = 0.f;
    float a4 = 0.f, a5 = 0.f, a6 = 0.f, a7 = 0.f;
#pragma unroll
    for (int l = 0; l < EB_L; l++) {
        if (l < n) {
            int id = s_ids[cl][l];                  // LDS broadcast, conflict-free
            const float* p = base + (size_t)id * EB_E;
            unsigned u0, u1, u2, u3, u4, u5, u6, u7;
            asm volatile(
                "ld.global.nc.L2::evict_last.v8.b32 "
                "{%0,%1,%2,%3,%4,%5,%6,%7}, [%8];"
                : "=r"(u0), "=r"(u1), "=r"(u2), "=r"(u3),
                  "=r"(u4), "=r"(u5), "=r"(u6), "=r"(u7)
                : "l"(p));
            a0 += __uint_as_float(u0); a1 += __uint_as_float(u1);
            a2 += __uint_as_float(u2); a3 += __uint_as_float(u3);
            a4 += __uint_as_float(u4); a5 += __uint_as_float(u5);
            a6 += __uint_as_float(u6); a7 += __uint_as_float(u7);
        }
    }

    // Streaming stores: written once, never re-read.
    float4* op = (float4*)(out + bf * EB_E + v * 8);
    __stcs(&op[0], make_float4(a0, a1, a2, a3));
    __stcs(&op[1], make_float4(a4, a5, a6, a7));
}

extern "C" void kernel_launch(void* const* d_in, const int* in_sizes, int n_in,
                              void* d_out, int out_size) {
    const int*   ids     = (const int*)d_in[0];     // int32 [B,F,L]
    const int*   lengths = (const int*)d_in[1];     // int32 [B,F]
    const float* tables  = (const float*)d_in[2];   // fp32  [F,V,E]
    float*       out     = (float*)d_out;           // fp32  [B,F*E]

    int total = EB_B * EB_F * EB_V8;                // 1,048,576 threads
    embbag_kernel<<<total / 128, 128>>>(ids, lengths, tables, out);
}